// round 6
// baseline (speedup 1.0000x reference)
#include <cuda_runtime.h>
#include <math.h>

#define N_INP 128
#define N_HID 512
#define N_OUT 256
#define N_HEADS 64
#define N_SM 4
#define EPS_GN 1e-5f
#define TINY 1e-14f

// Scratch + dependency counters: device globals (no allocation allowed).
__device__ float g_z1[N_HEADS * N_HID];         // pre-GN l1 activations
__device__ float g_z[N_SM * N_HEADS * N_OUT];   // pre-GN l2 activations [s][h][o]
__device__ float g_scalar[N_OUT * N_HEADS];     // ws.sum(-1).T, [o][h]
__device__ int c_z1[N_HEADS];                   // 4 producers per head
__device__ int c_z[N_HEADS];                    // 16 producers per head
__device__ int c_ws[N_HEADS];                   // 2 producers per head

__device__ __forceinline__ float wsum(float v) {
#pragma unroll
    for (int o = 16; o > 0; o >>= 1) v += __shfl_xor_sync(0xffffffffu, v, o);
    return v;
}
__device__ __forceinline__ float wmax(float v) {
#pragma unroll
    for (int o = 16; o > 0; o >>= 1) v = fmaxf(v, __shfl_xor_sync(0xffffffffu, v, o));
    return v;
}

__device__ __forceinline__ int ld_acq(const int* p) {
    int v;
    asm volatile("ld.acquire.gpu.s32 %0, [%1];" : "=r"(v) : "l"(p) : "memory");
    return v;
}
// Producer side: threadfence (release) then relaxed atomic increment.
__device__ __forceinline__ void release_inc(int* p) {
    __threadfence();
    atomicAdd(p, 1);
}
// Consumer side: thread 0 spins with acquire loads; syncthreads publishes to block.
__device__ __forceinline__ void spin_until(int* p, int tgt) {
    if (threadIdx.x == 0) {
        while (ld_acq(p) < tgt) __nanosleep(64);
    }
    __syncthreads();
}

__global__ __launch_bounds__(64) void kReset() {
    int t = threadIdx.x;
    c_z1[t] = 0;
    c_z[t] = 0;
    c_ws[t] = 0;
}

__global__ __launch_bounds__(256) void kMega(const float* __restrict__ x,
                                             const float* __restrict__ qw,
                                             const float* __restrict__ w1,
                                             const float* __restrict__ g1,
                                             const float* __restrict__ b1,
                                             const float* __restrict__ w2,
                                             const float* __restrict__ g2,
                                             const float* __restrict__ b2,
                                             const float* __restrict__ ws,
                                             const float* __restrict__ woo,
                                             const float* __restrict__ last,
                                             float* __restrict__ out) {
    int b = blockIdx.x;
    int t = threadIdx.x, w = t >> 5, l = t & 31;

    if (b < 128) {
        // ================= ws row-sums (no dependency) =================
        int h = b >> 1, half = b & 1;
        const float* base = ws + (size_t)h * 256 * 256 + (size_t)half * 128 * 256;
#pragma unroll
        for (int g = 0; g < 4; ++g) {
            int r = w * 16 + g * 4;
            float acc[4] = {0.f, 0.f, 0.f, 0.f};
            float4 a[8];
#pragma unroll
            for (int j = 0; j < 4; ++j)
#pragma unroll
                for (int k = 0; k < 2; ++k)
                    a[j * 2 + k] = *(const float4*)(base + (size_t)(r + j) * 256 + k * 128 + l * 4);
#pragma unroll
            for (int j = 0; j < 4; ++j)
#pragma unroll
                for (int k = 0; k < 2; ++k)
                    acc[j] += a[j * 2 + k].x + a[j * 2 + k].y + a[j * 2 + k].z + a[j * 2 + k].w;
#pragma unroll
            for (int j = 0; j < 4; ++j) acc[j] = wsum(acc[j]);
            if (l == 0) {
                int o = half * 128 + r;
#pragma unroll
                for (int j = 0; j < 4; ++j) g_scalar[(o + j) * 64 + h] = acc[j];
            }
        }
        __syncthreads();
        if (t == 0) release_inc(&c_ws[h]);

    } else if (b < 384) {
        // ================= kA: sub (redundant) + w1 chunk -> z1 =================
        int idx = b - 128;
        int h = idx >> 2, c = idx & 3;
        __shared__ float qs[128], sub[128];
        if (t < 128) qs[t] = qw[h * 128 + t];
        __syncthreads();
        float q0 = qs[l * 4], q1 = qs[l * 4 + 1], q2 = qs[l * 4 + 2], q3 = qs[l * 4 + 3];
#pragma unroll
        for (int g = 0; g < 2; ++g) {
            int r = w * 16 + g * 8;
            float4 a[8];
            float acc[8];
#pragma unroll
            for (int j = 0; j < 8; ++j)
                a[j] = *(const float4*)(x + (r + j) * 128 + l * 4);
#pragma unroll
            for (int j = 0; j < 8; ++j)
                acc[j] = a[j].x * q0 + a[j].y * q1 + a[j].z * q2 + a[j].w * q3;
#pragma unroll
            for (int j = 0; j < 8; ++j) acc[j] = wsum(acc[j]);
            if (l == 0) {
#pragma unroll
                for (int j = 0; j < 8; ++j) sub[r + j] = acc[j];
            }
        }
        __syncthreads();
        float s0 = sub[l * 4], s1 = sub[l * 4 + 1], s2 = sub[l * 4 + 2], s3 = sub[l * 4 + 3];
        const float* w1b = w1 + (size_t)h * 512 * 128 + (size_t)c * 128 * 128;
#pragma unroll
        for (int g = 0; g < 2; ++g) {
            int r = w * 16 + g * 8;
            float4 a[8];
            float acc[8];
#pragma unroll
            for (int j = 0; j < 8; ++j)
                a[j] = *(const float4*)(w1b + (r + j) * 128 + l * 4);
#pragma unroll
            for (int j = 0; j < 8; ++j)
                acc[j] = a[j].x * s0 + a[j].y * s1 + a[j].z * s2 + a[j].w * s3;
#pragma unroll
            for (int j = 0; j < 8; ++j) acc[j] = wsum(acc[j]);
            if (l == 0) {
#pragma unroll
                for (int j = 0; j < 8; ++j) g_z1[h * 512 + c * 128 + r + j] = acc[j];
            }
        }
        __syncthreads();
        if (t == 0) release_inc(&c_z1[h]);

    } else if (b < 1408) {
        // ================= w2 stream: GN1+softplus (redundant) + matvec chunk =================
        int idx = b - 384;
        int c = idx & 3, h = (idx >> 2) & 63, s = idx >> 8;
        __shared__ float h1s[512];
        __shared__ float rs[8], rss[8], stat[2];

        spin_until(&c_z1[h], 4);

        float v0 = g_z1[h * 512 + t], v1 = g_z1[h * 512 + 256 + t];
        float sv = v0 + v1, sq = v0 * v0 + v1 * v1;
        sv = wsum(sv); sq = wsum(sq);
        if (l == 0) { rs[w] = sv; rss[w] = sq; }
        __syncthreads();
        if (t == 0) {
            float S = 0.f, SS = 0.f;
#pragma unroll
            for (int i = 0; i < 8; ++i) { S += rs[i]; SS += rss[i]; }
            float mu = S / 512.f;
            float var = SS / 512.f - mu * mu;
            stat[0] = mu;
            stat[1] = rsqrtf(fmaxf(var, 0.f) + EPS_GN);
        }
        __syncthreads();
        float mu = stat[0], ri = stat[1];
        float a0 = (v0 - mu) * ri * g1[h * 512 + t] + b1[h * 512 + t];
        float a1 = (v1 - mu) * ri * g1[h * 512 + 256 + t] + b1[h * 512 + 256 + t];
        h1s[t] = fmaxf(a0, 0.f) + log1pf(expf(-fabsf(a0)));
        h1s[t + 256] = fmaxf(a1, 0.f) + log1pf(expf(-fabsf(a1)));
        __syncthreads();

        const float* base = w2 + ((size_t)(s * 64 + h)) * 256 * 512 + (size_t)c * 64 * 512;
#pragma unroll
        for (int g = 0; g < 4; ++g) {
            int r = w * 8 + g * 2;
            const float* r0 = base + (size_t)r * 512;
            const float* r1 = r0 + 512;
            float4 a[4], bq[4];
#pragma unroll
            for (int k = 0; k < 4; ++k) {
                a[k]  = *(const float4*)(r0 + k * 128 + l * 4);
                bq[k] = *(const float4*)(r1 + k * 128 + l * 4);
            }
            float d0 = 0.f, d1 = 0.f;
#pragma unroll
            for (int k = 0; k < 4; ++k) {
                int i = k * 128 + l * 4;
                d0 += a[k].x * h1s[i] + a[k].y * h1s[i + 1] + a[k].z * h1s[i + 2] + a[k].w * h1s[i + 3];
                d1 += bq[k].x * h1s[i] + bq[k].y * h1s[i + 1] + bq[k].z * h1s[i + 2] + bq[k].w * h1s[i + 3];
            }
            d0 = wsum(d0); d1 = wsum(d1);
            if (l == 0) {
                size_t o = (size_t)(s * 64 + h) * 256 + c * 64 + r;
                g_z[o] = d0;
                g_z[o + 1] = d1;
            }
        }
        __syncthreads();
        if (t == 0) release_inc(&c_z[h]);

    } else {
        // ================= final: GN2+softmax+sum_s + gate + outputs =================
        int h = b - 1408;
        __shared__ float r1[8], r2[8], stat[2];
        __shared__ float onoff_s;

        // last_prod (L2-resident, redundant per block)
        float lp;
        {
            const float* lo = last + t * 64;
            float p = 1.f;
#pragma unroll 8
            for (int i = 0; i < 64; ++i) p *= lo[i];
            lp = p;
        }

        if (t == 0) {
            while (ld_acq(&c_z[h]) < 16) __nanosleep(64);
            while (ld_acq(&c_ws[h]) < 2) __nanosleep(64);
        }
        __syncthreads();

        float acc = 0.f;
#pragma unroll
        for (int s = 0; s < 4; ++s) {
            size_t gi = (size_t)(s * 64 + h) * 256;
            float v = g_z[gi + t];
            float sv = wsum(v), sq = wsum(v * v);
            if (l == 0) { r1[w] = sv; r2[w] = sq; }
            __syncthreads();
            if (t == 0) {
                float S = 0.f, SS = 0.f;
#pragma unroll
                for (int i = 0; i < 8; ++i) { S += r1[i]; SS += r2[i]; }
                float mu = S / 256.f;
                float var = SS / 256.f - mu * mu;
                stat[0] = mu;
                stat[1] = rsqrtf(fmaxf(var, 0.f) + EPS_GN);
            }
            __syncthreads();
            float z = (v - stat[0]) * stat[1] * g2[gi + t] + b2[gi + t];
            __syncthreads();
            float m = wmax(z);
            if (l == 0) r1[w] = m;
            __syncthreads();
            if (t == 0) {
                float M = -1e30f;
#pragma unroll
                for (int i = 0; i < 8; ++i) M = fmaxf(M, r1[i]);
                stat[0] = M;
            }
            __syncthreads();
            float e = expf(z - stat[0]);
            float se = wsum(e);
            if (l == 0) r2[w] = se;
            __syncthreads();
            if (t == 0) {
                float S = 0.f;
#pragma unroll
                for (int i = 0; i < 8; ++i) S += r2[i];
                stat[1] = S;
            }
            __syncthreads();
            acc += e / stat[1];
            __syncthreads();
        }

        float gp = woo[h * 512 + t] * lp + woo[h * 512 + 256 + t] * acc;
        gp = wsum(gp);
        if (l == 0) r1[w] = gp;
        __syncthreads();
        if (t == 0) {
            float S = 0.f;
#pragma unroll
            for (int i = 0; i < 8; ++i) S += r1[i];
            onoff_s = 1.f / (1.f + expf(-S));
        }
        __syncthreads();

        float v = onoff_s * acc;
        out[t * 64 + h] = fmaxf(v, TINY);
        float sc = v * g_scalar[t * 64 + h];
        out[16384 + t * 64 + h] = (fabsf(sc) <= TINY) ? TINY : sc;
    }
}

extern "C" void kernel_launch(void* const* d_in, const int* in_sizes, int n_in,
                              void* d_out, int out_size) {
    const float* x    = (const float*)d_in[0];
    const float* last = (const float*)d_in[1];
    const float* qw   = (const float*)d_in[2];
    const float* w1   = (const float*)d_in[3];
    const float* g1   = (const float*)d_in[4];
    const float* b1   = (const float*)d_in[5];
    const float* w2   = (const float*)d_in[6];
    const float* g2   = (const float*)d_in[7];
    const float* b2   = (const float*)d_in[8];
    const float* ws   = (const float*)d_in[9];
    const float* woo  = (const float*)d_in[10];
    float* out = (float*)d_out;

    kReset<<<1, 64>>>();
    kMega<<<1472, 256>>>(x, qw, w1, g1, b1, w2, g2, b2, ws, woo, last, out);
}

// round 7
// speedup vs baseline: 1.1241x; 1.1241x over previous
#include <cuda_runtime.h>
#include <math.h>

#define N_INP 128
#define N_HID 512
#define N_OUT 256
#define N_HEADS 64
#define N_SM 4
#define EPS_GN 1e-5f
#define TINY 1e-14f

// Scratch: device globals (no allocation allowed).
__device__ float g_z1[N_HEADS * N_HID];         // pre-GN l1 activations
__device__ float g_z[N_SM * N_HEADS * N_OUT];   // pre-GN l2 activations [s][h][o]
__device__ float g_scalar[N_OUT * N_HEADS];     // ws.sum(-1).T, [o][h]

__device__ __forceinline__ float wsum(float v) {
#pragma unroll
    for (int o = 16; o > 0; o >>= 1) v += __shfl_xor_sync(0xffffffffu, v, o);
    return v;
}
__device__ __forceinline__ float wmax(float v) {
#pragma unroll
    for (int o = 16; o > 0; o >>= 1) v = fmaxf(v, __shfl_xor_sync(0xffffffffu, v, o));
    return v;
}

// ---------------- k1: ws row-sums (128 blocks) + [sub + w1 chunk] (256 blocks) ----------------
__global__ __launch_bounds__(256) void k1(const float* __restrict__ x,
                                          const float* __restrict__ qw,
                                          const float* __restrict__ w1,
                                          const float* __restrict__ ws) {
    int b = blockIdx.x;
    int t = threadIdx.x, w = t >> 5, l = t & 31;

    if (b < 128) {
        // ws row-sums: scalar[o][h] = sum_j ws[h][o][j] — pure DRAM stream, no deps
        int h = b >> 1, half = b & 1;
        const float* base = ws + (size_t)h * 256 * 256 + (size_t)half * 128 * 256;
#pragma unroll
        for (int g = 0; g < 4; ++g) {
            int r = w * 16 + g * 4;
            float acc[4] = {0.f, 0.f, 0.f, 0.f};
            float4 a[8];
#pragma unroll
            for (int j = 0; j < 4; ++j)
#pragma unroll
                for (int k = 0; k < 2; ++k)
                    a[j * 2 + k] = *(const float4*)(base + (size_t)(r + j) * 256 + k * 128 + l * 4);
#pragma unroll
            for (int j = 0; j < 4; ++j)
#pragma unroll
                for (int k = 0; k < 2; ++k)
                    acc[j] += a[j * 2 + k].x + a[j * 2 + k].y + a[j * 2 + k].z + a[j * 2 + k].w;
#pragma unroll
            for (int j = 0; j < 4; ++j) acc[j] = wsum(acc[j]);
            if (l == 0) {
                int o = half * 128 + r;
#pragma unroll
                for (int j = 0; j < 4; ++j) g_scalar[(o + j) * 64 + h] = acc[j];
            }
        }
    } else {
        // sub (redundant per block, L2-resident x) + w1 chunk matvec -> z1
        int idx = b - 128;
        int h = idx >> 2, c = idx & 3;
        __shared__ float qs[128], sub[128];
        if (t < 128) qs[t] = qw[h * 128 + t];
        __syncthreads();
        float q0 = qs[l * 4], q1 = qs[l * 4 + 1], q2 = qs[l * 4 + 2], q3 = qs[l * 4 + 3];
#pragma unroll
        for (int g = 0; g < 2; ++g) {
            int r = w * 16 + g * 8;
            float4 a[8];
            float acc[8];
#pragma unroll
            for (int j = 0; j < 8; ++j)
                a[j] = *(const float4*)(x + (r + j) * 128 + l * 4);
#pragma unroll
            for (int j = 0; j < 8; ++j)
                acc[j] = a[j].x * q0 + a[j].y * q1 + a[j].z * q2 + a[j].w * q3;
#pragma unroll
            for (int j = 0; j < 8; ++j) acc[j] = wsum(acc[j]);
            if (l == 0) {
#pragma unroll
                for (int j = 0; j < 8; ++j) sub[r + j] = acc[j];
            }
        }
        __syncthreads();
        float s0 = sub[l * 4], s1 = sub[l * 4 + 1], s2 = sub[l * 4 + 2], s3 = sub[l * 4 + 3];
        const float* w1b = w1 + (size_t)h * 512 * 128 + (size_t)c * 128 * 128;
#pragma unroll
        for (int g = 0; g < 2; ++g) {
            int r = w * 16 + g * 8;
            float4 a[8];
            float acc[8];
#pragma unroll
            for (int j = 0; j < 8; ++j)
                a[j] = *(const float4*)(w1b + (r + j) * 128 + l * 4);
#pragma unroll
            for (int j = 0; j < 8; ++j)
                acc[j] = a[j].x * s0 + a[j].y * s1 + a[j].z * s2 + a[j].w * s3;
#pragma unroll
            for (int j = 0; j < 8; ++j) acc[j] = wsum(acc[j]);
            if (l == 0) {
#pragma unroll
                for (int j = 0; j < 8; ++j) g_z1[h * 512 + c * 128 + r + j] = acc[j];
            }
        }
    }
}

// ---------------- k2: GN1+softplus (redundant per block) + w2 stream ----------------
__global__ __launch_bounds__(256) void k2(const float* __restrict__ w2,
                                          const float* __restrict__ g1,
                                          const float* __restrict__ b1) {
    int b = blockIdx.x;
    int t = threadIdx.x, w = t >> 5, l = t & 31;
    int c = b & 3, h = (b >> 2) & 63, s = b >> 8;
    __shared__ float h1s[512];
    __shared__ float rs[8], rss[8], stat[2];

    // GN1 + softplus on z1[h] (L2-resident; recomputed per block)
    float v0 = g_z1[h * 512 + t], v1 = g_z1[h * 512 + 256 + t];
    float sv = v0 + v1, sq = v0 * v0 + v1 * v1;
    sv = wsum(sv); sq = wsum(sq);
    if (l == 0) { rs[w] = sv; rss[w] = sq; }
    __syncthreads();
    if (t == 0) {
        float S = 0.f, SS = 0.f;
#pragma unroll
        for (int i = 0; i < 8; ++i) { S += rs[i]; SS += rss[i]; }
        float mu = S / 512.f;
        float var = SS / 512.f - mu * mu;
        stat[0] = mu;
        stat[1] = rsqrtf(fmaxf(var, 0.f) + EPS_GN);
    }
    __syncthreads();
    float mu = stat[0], ri = stat[1];
    float a0 = (v0 - mu) * ri * g1[h * 512 + t] + b1[h * 512 + t];
    float a1 = (v1 - mu) * ri * g1[h * 512 + 256 + t] + b1[h * 512 + 256 + t];
    h1s[t] = fmaxf(a0, 0.f) + log1pf(expf(-fabsf(a0)));
    h1s[t + 256] = fmaxf(a1, 0.f) + log1pf(expf(-fabsf(a1)));
    __syncthreads();

    const float* base = w2 + ((size_t)(s * 64 + h)) * 256 * 512 + (size_t)c * 64 * 512;
    // 64 rows, 8 warps -> 8 rows/warp; 2-row x 4-kchunk ILP = 8 LDG.128 in flight
#pragma unroll
    for (int g = 0; g < 4; ++g) {
        int r = w * 8 + g * 2;
        const float* r0 = base + (size_t)r * 512;
        const float* r1 = r0 + 512;
        float4 a[4], bq[4];
#pragma unroll
        for (int k = 0; k < 4; ++k) {
            a[k]  = *(const float4*)(r0 + k * 128 + l * 4);
            bq[k] = *(const float4*)(r1 + k * 128 + l * 4);
        }
        float d0 = 0.f, d1 = 0.f;
#pragma unroll
        for (int k = 0; k < 4; ++k) {
            int i = k * 128 + l * 4;
            d0 += a[k].x * h1s[i] + a[k].y * h1s[i + 1] + a[k].z * h1s[i + 2] + a[k].w * h1s[i + 3];
            d1 += bq[k].x * h1s[i] + bq[k].y * h1s[i + 1] + bq[k].z * h1s[i + 2] + bq[k].w * h1s[i + 3];
        }
        d0 = wsum(d0); d1 = wsum(d1);
        if (l == 0) {
            size_t o = (size_t)(s * 64 + h) * 256 + c * 64 + r;
            g_z[o] = d0;
            g_z[o + 1] = d1;
        }
    }
}

// ---------------- k3: per-head GN2+softmax+sum_s + gate + final outputs ----------------
__global__ __launch_bounds__(256) void k3(const float* __restrict__ g2,
                                          const float* __restrict__ b2,
                                          const float* __restrict__ woo,
                                          const float* __restrict__ last,
                                          float* __restrict__ out) {
    int h = blockIdx.x, t = threadIdx.x, w = t >> 5, l = t & 31;
    __shared__ float r1[8], r2[8], stat[2];
    __shared__ float onoff_s;

    // last_prod[t] (redundant per block, L2-resident)
    float lp;
    {
        const float* lo = last + t * 64;
        float p = 1.f;
#pragma unroll 8
        for (int i = 0; i < 64; ++i) p *= lo[i];
        lp = p;
    }

    float acc = 0.f;
#pragma unroll
    for (int s = 0; s < 4; ++s) {
        size_t gi = (size_t)(s * 64 + h) * 256;
        float v = g_z[gi + t];
        float sv = wsum(v), sq = wsum(v * v);
        if (l == 0) { r1[w] = sv; r2[w] = sq; }
        __syncthreads();
        if (t == 0) {
            float S = 0.f, SS = 0.f;
#pragma unroll
            for (int i = 0; i < 8; ++i) { S += r1[i]; SS += r2[i]; }
            float mu = S / 256.f;
            float var = SS / 256.f - mu * mu;
            stat[0] = mu;
            stat[1] = rsqrtf(fmaxf(var, 0.f) + EPS_GN);
        }
        __syncthreads();
        float z = (v - stat[0]) * stat[1] * g2[gi + t] + b2[gi + t];
        __syncthreads();
        float m = wmax(z);
        if (l == 0) r1[w] = m;
        __syncthreads();
        if (t == 0) {
            float M = -1e30f;
#pragma unroll
            for (int i = 0; i < 8; ++i) M = fmaxf(M, r1[i]);
            stat[0] = M;
        }
        __syncthreads();
        float e = expf(z - stat[0]);
        float se = wsum(e);
        if (l == 0) r2[w] = se;
        __syncthreads();
        if (t == 0) {
            float S = 0.f;
#pragma unroll
            for (int i = 0; i < 8; ++i) S += r2[i];
            stat[1] = S;
        }
        __syncthreads();
        acc += e / stat[1];
        __syncthreads();
    }

    // gate: woo[h,:256] @ last_prod + woo[h,256:] @ outsm[:,h]
    float gp = woo[h * 512 + t] * lp + woo[h * 512 + 256 + t] * acc;
    gp = wsum(gp);
    if (l == 0) r1[w] = gp;
    __syncthreads();
    if (t == 0) {
        float S = 0.f;
#pragma unroll
        for (int i = 0; i < 8; ++i) S += r1[i];
        onoff_s = 1.f / (1.f + expf(-S));
    }
    __syncthreads();

    float v = onoff_s * acc;
    out[t * 64 + h] = fmaxf(v, TINY);
    float sc = v * g_scalar[t * 64 + h];
    out[16384 + t * 64 + h] = (fabsf(sc) <= TINY) ? TINY : sc;
}

extern "C" void kernel_launch(void* const* d_in, const int* in_sizes, int n_in,
                              void* d_out, int out_size) {
    const float* x    = (const float*)d_in[0];
    const float* last = (const float*)d_in[1];
    const float* qw   = (const float*)d_in[2];
    const float* w1   = (const float*)d_in[3];
    const float* g1   = (const float*)d_in[4];
    const float* b1   = (const float*)d_in[5];
    const float* w2   = (const float*)d_in[6];
    const float* g2   = (const float*)d_in[7];
    const float* b2   = (const float*)d_in[8];
    const float* ws   = (const float*)d_in[9];
    const float* woo  = (const float*)d_in[10];
    float* out = (float*)d_out;

    k1<<<384, 256>>>(x, qw, w1, ws);
    k2<<<1024, 256>>>(w2, g1, b1);
    k3<<<64, 256>>>(g2, b2, woo, last, out);
}

// round 8
// speedup vs baseline: 1.3974x; 1.2431x over previous
#include <cuda_runtime.h>
#include <math.h>

#define N_INP 128
#define N_HID 512
#define N_OUT 256
#define N_HEADS 64
#define N_SM 4
#define EPS_GN 1e-5f
#define TINY 1e-14f

// Scratch: device globals (no allocation allowed).
__device__ float g_z1[N_HEADS * N_HID];         // pre-GN l1 activations
__device__ float g_z[N_SM * N_HEADS * N_OUT];   // pre-GN l2 activations [s][h][o]
__device__ float g_scalar[N_OUT * N_HEADS];     // ws.sum(-1).T, [o][h]

__device__ __forceinline__ float wsum(float v) {
#pragma unroll
    for (int o = 16; o > 0; o >>= 1) v += __shfl_xor_sync(0xffffffffu, v, o);
    return v;
}
__device__ __forceinline__ float wmax(float v) {
#pragma unroll
    for (int o = 16; o > 0; o >>= 1) v = fmaxf(v, __shfl_xor_sync(0xffffffffu, v, o));
    return v;
}

// ---------------- kA: fused sub = x@qw_h (redundant per block) + w1 chunk matvec ----------------
__global__ __launch_bounds__(256) void kA(const float* __restrict__ x,
                                          const float* __restrict__ qw,
                                          const float* __restrict__ w1) {
    int h = blockIdx.x >> 2, c = blockIdx.x & 3;
    int t = threadIdx.x, w = t >> 5, l = t & 31;
    __shared__ float qs[128], sub[128];
    if (t < 128) qs[t] = qw[h * 128 + t];
    __syncthreads();
    float q0 = qs[l * 4], q1 = qs[l * 4 + 1], q2 = qs[l * 4 + 2], q3 = qs[l * 4 + 3];

    // sub[r] = dot(x[r,:], qw[h,:]) — 8 warps × 16 rows, 8-row ILP (x is L2-resident)
#pragma unroll
    for (int g = 0; g < 2; ++g) {
        int r = w * 16 + g * 8;
        float4 a[8];
        float acc[8];
#pragma unroll
        for (int j = 0; j < 8; ++j)
            a[j] = *(const float4*)(x + (r + j) * 128 + l * 4);
#pragma unroll
        for (int j = 0; j < 8; ++j)
            acc[j] = a[j].x * q0 + a[j].y * q1 + a[j].z * q2 + a[j].w * q3;
#pragma unroll
        for (int j = 0; j < 8; ++j) acc[j] = wsum(acc[j]);
        if (l == 0) {
#pragma unroll
            for (int j = 0; j < 8; ++j) sub[r + j] = acc[j];
        }
    }
    __syncthreads();

    float s0 = sub[l * 4], s1 = sub[l * 4 + 1], s2 = sub[l * 4 + 2], s3 = sub[l * 4 + 3];
    const float* w1b = w1 + (size_t)h * 512 * 128 + (size_t)c * 128 * 128;
    // 128 rows per block, 8 warps -> 16 rows/warp, 8-row ILP
#pragma unroll
    for (int g = 0; g < 2; ++g) {
        int r = w * 16 + g * 8;
        float4 a[8];
        float acc[8];
#pragma unroll
        for (int j = 0; j < 8; ++j)
            a[j] = *(const float4*)(w1b + (r + j) * 128 + l * 4);
#pragma unroll
        for (int j = 0; j < 8; ++j)
            acc[j] = a[j].x * s0 + a[j].y * s1 + a[j].z * s2 + a[j].w * s3;
#pragma unroll
        for (int j = 0; j < 8; ++j) acc[j] = wsum(acc[j]);
        if (l == 0) {
#pragma unroll
            for (int j = 0; j < 8; ++j) g_z1[h * 512 + c * 128 + r + j] = acc[j];
        }
    }
}

// ---------------- kB: fused GN1+softplus (redundant) + w2 stream (16-load batches) + ws sums ----------------
__global__ __launch_bounds__(256, 3) void kB(const float* __restrict__ w2,
                                             const float* __restrict__ ws,
                                             const float* __restrict__ g1,
                                             const float* __restrict__ b1) {
    int b = blockIdx.x;
    int t = threadIdx.x, w = t >> 5, l = t & 31;
    if (b < 1024) {
        int c = b & 3, h = (b >> 2) & 63, s = b >> 8;
        __shared__ float h1s[512];
        __shared__ float rs[8], rss[8], stat[2];

        // GN1 + softplus on z1[h] (L2-resident; recomputed per block)
        float v0 = g_z1[h * 512 + t], v1 = g_z1[h * 512 + 256 + t];
        float sv = v0 + v1, sq = v0 * v0 + v1 * v1;
        sv = wsum(sv); sq = wsum(sq);
        if (l == 0) { rs[w] = sv; rss[w] = sq; }
        __syncthreads();
        if (t == 0) {
            float S = 0.f, SS = 0.f;
#pragma unroll
            for (int i = 0; i < 8; ++i) { S += rs[i]; SS += rss[i]; }
            float mu = S / 512.f;
            float var = SS / 512.f - mu * mu;
            stat[0] = mu;
            stat[1] = rsqrtf(fmaxf(var, 0.f) + EPS_GN);
        }
        __syncthreads();
        float mu = stat[0], ri = stat[1];
        float a0 = (v0 - mu) * ri * g1[h * 512 + t] + b1[h * 512 + t];
        float a1 = (v1 - mu) * ri * g1[h * 512 + 256 + t] + b1[h * 512 + 256 + t];
        h1s[t] = fmaxf(a0, 0.f) + log1pf(expf(-fabsf(a0)));
        h1s[t + 256] = fmaxf(a1, 0.f) + log1pf(expf(-fabsf(a1)));
        __syncthreads();

        const float* base = w2 + ((size_t)(s * 64 + h)) * 256 * 512 + (size_t)c * 64 * 512;
        // 64 rows, 8 warps -> 8 rows/warp; 4-row x 4-kchunk batch = 16 LDG.128 in flight
#pragma unroll
        for (int g = 0; g < 2; ++g) {
            int r = w * 8 + g * 4;
            const float* rp = base + (size_t)r * 512;
            float4 a[16];
#pragma unroll
            for (int j = 0; j < 4; ++j)
#pragma unroll
                for (int k = 0; k < 4; ++k)
                    a[j * 4 + k] = *(const float4*)(rp + (size_t)j * 512 + k * 128 + l * 4);
            float d[4] = {0.f, 0.f, 0.f, 0.f};
#pragma unroll
            for (int j = 0; j < 4; ++j)
#pragma unroll
                for (int k = 0; k < 4; ++k) {
                    int i = k * 128 + l * 4;
                    float4 q = a[j * 4 + k];
                    d[j] += q.x * h1s[i] + q.y * h1s[i + 1] + q.z * h1s[i + 2] + q.w * h1s[i + 3];
                }
#pragma unroll
            for (int j = 0; j < 4; ++j) d[j] = wsum(d[j]);
            if (l == 0) {
                size_t o = (size_t)(s * 64 + h) * 256 + c * 64 + r;
#pragma unroll
                for (int j = 0; j < 4; ++j) g_z[o + j] = d[j];
            }
        }
    } else {
        // ws row-sums: scalar[o][h] = sum_j ws[h][o][j]
        int idx = b - 1024;
        int h = idx >> 1, half = idx & 1;
        const float* base = ws + (size_t)h * 256 * 256 + (size_t)half * 128 * 256;
#pragma unroll
        for (int g = 0; g < 2; ++g) {
            int r = w * 16 + g * 8;
            float acc[8] = {0.f, 0.f, 0.f, 0.f, 0.f, 0.f, 0.f, 0.f};
            float4 a[16];
#pragma unroll
            for (int j = 0; j < 8; ++j)
#pragma unroll
                for (int k = 0; k < 2; ++k)
                    a[j * 2 + k] = *(const float4*)(base + (size_t)(r + j) * 256 + k * 128 + l * 4);
#pragma unroll
            for (int j = 0; j < 8; ++j)
#pragma unroll
                for (int k = 0; k < 2; ++k)
                    acc[j] += a[j * 2 + k].x + a[j * 2 + k].y + a[j * 2 + k].z + a[j * 2 + k].w;
#pragma unroll
            for (int j = 0; j < 8; ++j) acc[j] = wsum(acc[j]);
            if (l == 0) {
                int o = half * 128 + r;
#pragma unroll
                for (int j = 0; j < 8; ++j) g_scalar[(o + j) * 64 + h] = acc[j];
            }
        }
    }
}

// ---------------- kC: per-head GN2+softmax+sum_s + full gate + final outputs ----------------
__global__ __launch_bounds__(256) void kC(const float* __restrict__ g2,
                                          const float* __restrict__ b2,
                                          const float* __restrict__ woo,
                                          const float* __restrict__ last,
                                          float* __restrict__ out) {
    int h = blockIdx.x, t = threadIdx.x, w = t >> 5, l = t & 31;
    __shared__ float r1[8], r2[8], stat[2];
    __shared__ float onoff_s;

    // last_prod[t] = prod over heads of last[t, :]  (redundant per block, L2-resident)
    float lp;
    {
        const float* lo = last + t * 64;
        float p = 1.f;
#pragma unroll 8
        for (int i = 0; i < 64; ++i) p *= lo[i];
        lp = p;
    }

    float acc = 0.f;
#pragma unroll
    for (int s = 0; s < 4; ++s) {
        size_t gi = (size_t)(s * 64 + h) * 256;
        float v = g_z[gi + t];
        float sv = wsum(v), sq = wsum(v * v);
        if (l == 0) { r1[w] = sv; r2[w] = sq; }
        __syncthreads();
        if (t == 0) {
            float S = 0.f, SS = 0.f;
#pragma unroll
            for (int i = 0; i < 8; ++i) { S += r1[i]; SS += r2[i]; }
            float mu = S / 256.f;
            float var = SS / 256.f - mu * mu;
            stat[0] = mu;
            stat[1] = rsqrtf(fmaxf(var, 0.f) + EPS_GN);
        }
        __syncthreads();
        float z = (v - stat[0]) * stat[1] * g2[gi + t] + b2[gi + t];
        __syncthreads();
        float m = wmax(z);
        if (l == 0) r1[w] = m;
        __syncthreads();
        if (t == 0) {
            float M = -1e30f;
#pragma unroll
            for (int i = 0; i < 8; ++i) M = fmaxf(M, r1[i]);
            stat[0] = M;
        }
        __syncthreads();
        float e = expf(z - stat[0]);
        float se = wsum(e);
        if (l == 0) r2[w] = se;
        __syncthreads();
        if (t == 0) {
            float S = 0.f;
#pragma unroll
            for (int i = 0; i < 8; ++i) S += r2[i];
            stat[1] = S;
        }
        __syncthreads();
        acc += e / stat[1];
        __syncthreads();
    }

    // gate: woo[h,:256] @ lp + woo[h,256:] @ outsm[:,h]
    float gp = woo[h * 512 + t] * lp + woo[h * 512 + 256 + t] * acc;
    gp = wsum(gp);
    if (l == 0) r1[w] = gp;
    __syncthreads();
    if (t == 0) {
        float S = 0.f;
#pragma unroll
        for (int i = 0; i < 8; ++i) S += r1[i];
        onoff_s = 1.f / (1.f + expf(-S));
    }
    __syncthreads();

    float v = onoff_s * acc;
    out[t * 64 + h] = fmaxf(v, TINY);
    float sc = v * g_scalar[t * 64 + h];
    out[16384 + t * 64 + h] = (fabsf(sc) <= TINY) ? TINY : sc;
}

extern "C" void kernel_launch(void* const* d_in, const int* in_sizes, int n_in,
                              void* d_out, int out_size) {
    const float* x    = (const float*)d_in[0];
    const float* last = (const float*)d_in[1];
    const float* qw   = (const float*)d_in[2];
    const float* w1   = (const float*)d_in[3];
    const float* g1   = (const float*)d_in[4];
    const float* b1   = (const float*)d_in[5];
    const float* w2   = (const float*)d_in[6];
    const float* g2   = (const float*)d_in[7];
    const float* b2   = (const float*)d_in[8];
    const float* ws   = (const float*)d_in[9];
    const float* woo  = (const float*)d_in[10];
    float* out = (float*)d_out;

    kA<<<256, 256>>>(x, qw, w1);
    kB<<<1152, 256>>>(w2, ws, g1, b1);
    kC<<<64, 256>>>(g2, b2, woo, last, out);
}